// round 2
// baseline (speedup 1.0000x reference)
#include <cuda_runtime.h>

#define N_NODES 100000
#define NE      1600000
#define FIN     1433
#define HD      64
#define NH      2
#define NC      7
#define OC      14   // NH*NC

// ---------------- scratch (static device globals; no allocation) ----------------
__device__ float g_deg [N_NODES];
__device__ float g_dinv[N_NODES];
__device__ float g_bufA[N_NODES * HD];   // transformed features (x@W1, then h1@W2)
__device__ float g_bufB[N_NODES * HD];   // aggregated features
__device__ float g_hg  [N_NODES * OC];   // GAT transformed features
__device__ float g_as  [N_NODES * NH];   // a_src per node/head
__device__ float g_ad  [N_NODES * NH];   // a_dst per node/head
__device__ int   g_menc[N_NODES * NH];   // encoded segment max
__device__ float g_m   [N_NODES * NH];   // decoded segment max
__device__ float g_sum [N_NODES * NH];   // segment softmax denominator
__device__ float g_aggG[N_NODES * OC];   // GAT aggregation

// ---------------- helpers ----------------
__device__ __forceinline__ float lrelu(float x) { return x > 0.f ? x : 0.2f * x; }

// order-preserving float<->int encoding for atomicMax
__device__ __forceinline__ int   enc_f(float f) { int i = __float_as_int(f); return i >= 0 ? i : i ^ 0x7fffffff; }
__device__ __forceinline__ float dec_f(int i)   { return __int_as_float(i >= 0 ? i : i ^ 0x7fffffff); }

// ---------------- degree / normalization ----------------
__global__ void k_deg_init() {
    int i = blockIdx.x * blockDim.x + threadIdx.x;
    if (i < N_NODES) g_deg[i] = 1.0f;  // self-loop
}
__global__ void k_deg_edge(const int* __restrict__ dst) {
    int e = blockIdx.x * blockDim.x + threadIdx.x;
    if (e < NE) atomicAdd(&g_deg[dst[e]], 1.0f);
}
__global__ void k_dinv() {
    int i = blockIdx.x * blockDim.x + threadIdx.x;
    if (i < N_NODES) g_dinv[i] = rsqrtf(g_deg[i]);
}

// ---------------- GEMM1: g_bufA = x @ W1   [100000,1433]x[1433,64] ----------------
// 128x64 block tile, BK=16, 256 threads, each thread 8x4 micro-tile.
__global__ void __launch_bounds__(256) k_gemm1(const float* __restrict__ X,
                                               const float* __restrict__ W) {
    __shared__ float As[16][132];   // [k][row], padded
    __shared__ float Bs[16][64];    // [k][col]
    const int block_row = blockIdx.x * 128;
    const int t  = threadIdx.x;
    const int tr = t >> 4;   // 0..15 -> rows tr*8..tr*8+7
    const int tc = t & 15;   // 0..15 -> cols tc*4..tc*4+3

    float acc[8][4];
#pragma unroll
    for (int i = 0; i < 8; i++)
#pragma unroll
        for (int j = 0; j < 4; j++) acc[i][j] = 0.f;

    for (int k0 = 0; k0 < FIN; k0 += 16) {
        // load A tile: thread t loads 8 consecutive of 2048
#pragma unroll
        for (int i = 0; i < 8; i++) {
            int idx = t * 8 + i;
            int r = idx >> 4, k = idx & 15;
            int gr = block_row + r, gk = k0 + k;
            float v = 0.f;
            if (gr < N_NODES && gk < FIN) v = X[gr * FIN + gk];
            As[k][r] = v;
        }
        // load B tile: 16x64
#pragma unroll
        for (int i = 0; i < 4; i++) {
            int idx = t + i * 256;
            int k = idx >> 6, c = idx & 63;
            int gk = k0 + k;
            Bs[k][c] = (gk < FIN) ? W[gk * HD + c] : 0.f;
        }
        __syncthreads();
#pragma unroll
        for (int kk = 0; kk < 16; kk++) {
            float4 a0 = *(const float4*)&As[kk][tr * 8];
            float4 a1 = *(const float4*)&As[kk][tr * 8 + 4];
            float4 b  = *(const float4*)&Bs[kk][tc * 4];
            float av[8] = {a0.x, a0.y, a0.z, a0.w, a1.x, a1.y, a1.z, a1.w};
            float bv[4] = {b.x, b.y, b.z, b.w};
#pragma unroll
            for (int i = 0; i < 8; i++)
#pragma unroll
                for (int j = 0; j < 4; j++) acc[i][j] += av[i] * bv[j];
        }
        __syncthreads();
    }
#pragma unroll
    for (int i = 0; i < 8; i++) {
        int gr = block_row + tr * 8 + i;
        if (gr < N_NODES) {
#pragma unroll
            for (int j = 0; j < 4; j++)
                g_bufA[gr * HD + tc * 4 + j] = acc[i][j];
        }
    }
}

// ---------------- GCN propagation: bufB = scatter(bufA) ----------------
// init with self-loop contribution
__global__ void k_scatter_self() {
    int tid = blockIdx.x * blockDim.x + threadIdx.x;
    if (tid >= N_NODES * 16) return;
    int i = tid >> 4, l = tid & 15;
    float di = g_dinv[i];
    float s = di * di;
    float4 v = ((const float4*)(g_bufA + i * HD))[l];
    v.x *= s; v.y *= s; v.z *= s; v.w *= s;
    ((float4*)(g_bufB + i * HD))[l] = v;
}
__global__ void k_scatter_edge(const int* __restrict__ src, const int* __restrict__ dst) {
    int tid = blockIdx.x * blockDim.x + threadIdx.x;
    if (tid >= NE * 16) return;
    int e = tid >> 4, l = tid & 15;
    int s = src[e], d = dst[e];
    float nrm = g_dinv[s] * g_dinv[d];
    float4 v = ((const float4*)(g_bufA + s * HD))[l];
    v.x *= nrm; v.y *= nrm; v.z *= nrm; v.w *= nrm;
    atomicAdd(((float4*)(g_bufB + d * HD)) + l, v);
}

// ---------------- GEMM2: bufA = relu(bufB + b1) @ W2   (64x64) ----------------
__global__ void __launch_bounds__(256) k_gemm2(const float* __restrict__ bias,
                                               const float* __restrict__ W) {
    __shared__ float Ws[HD * HD];
    __shared__ float As[16][HD];
    const int t = threadIdx.x;
    const int rows = blockIdx.x * 16;
#pragma unroll
    for (int i = 0; i < 16; i++) Ws[t + i * 256] = W[t + i * 256];
#pragma unroll
    for (int i = 0; i < 4; i++) {
        int idx = t + i * 256;
        int r = idx >> 6, c = idx & 63;
        int gr = rows + r;
        float v = 0.f;
        if (gr < N_NODES) v = fmaxf(g_bufB[gr * HD + c] + bias[c], 0.f);
        As[r][c] = v;
    }
    __syncthreads();
    int r = t >> 4, cg = t & 15;
    float acc[4] = {0.f, 0.f, 0.f, 0.f};
#pragma unroll
    for (int k = 0; k < HD; k++) {
        float a = As[r][k];
#pragma unroll
        for (int j = 0; j < 4; j++) acc[j] += a * Ws[k * HD + cg + 16 * j];
    }
    int gr = rows + r;
    if (gr < N_NODES) {
#pragma unroll
        for (int j = 0; j < 4; j++) g_bufA[gr * HD + cg + 16 * j] = acc[j];
    }
}

// ---------------- GAT transform: hg = relu(bufB + b2) @ Wg  (64x14, warp/node) ----------------
__global__ void k_gat_transform(const float* __restrict__ bias, const float* __restrict__ Wg) {
    __shared__ float Ws[HD * OC];
    int t = threadIdx.x;
    for (int idx = t; idx < HD * OC; idx += blockDim.x) Ws[idx] = Wg[idx];
    __syncthreads();
    int node = (blockIdx.x * blockDim.x + t) >> 5;
    int lane = t & 31;
    if (node >= N_NODES) return;
    float f_lo = fmaxf(g_bufB[node * HD + lane]      + bias[lane],      0.f);
    float f_hi = fmaxf(g_bufB[node * HD + 32 + lane] + bias[32 + lane], 0.f);
    int c = lane < OC ? lane : 0;
    float acc = 0.f;
#pragma unroll
    for (int k = 0; k < 32; k++) {
        float a = __shfl_sync(0xffffffffu, f_lo, k);
        acc += a * Ws[k * OC + c];
    }
#pragma unroll
    for (int k = 0; k < 32; k++) {
        float a = __shfl_sync(0xffffffffu, f_hi, k);
        acc += a * Ws[(k + 32) * OC + c];
    }
    if (lane < OC) g_hg[node * OC + lane] = acc;
}

// ---------------- attention scalars + max init (self-loop) ----------------
__global__ void k_node_att(const float* __restrict__ att_src, const float* __restrict__ att_dst) {
    int tid = blockIdx.x * blockDim.x + threadIdx.x;
    if (tid >= N_NODES * NH) return;
    int i = tid >> 1, h = tid & 1;
    const float* hrow = g_hg + i * OC + h * NC;
    float as = 0.f, ad = 0.f;
#pragma unroll
    for (int c = 0; c < NC; c++) {
        as += hrow[c] * att_src[h * NC + c];
        ad += hrow[c] * att_dst[h * NC + c];
    }
    g_as[tid] = as;
    g_ad[tid] = ad;
    g_menc[tid] = enc_f(lrelu(as + ad));   // self-loop seeds segment max
}
__global__ void k_edge_max(const int* __restrict__ src, const int* __restrict__ dst) {
    int tid = blockIdx.x * blockDim.x + threadIdx.x;
    if (tid >= NE * NH) return;
    int e = tid >> 1, h = tid & 1;
    int s = src[e], d = dst[e];
    float ev = lrelu(g_as[s * NH + h] + g_ad[d * NH + h]);
    atomicMax(&g_menc[d * NH + h], enc_f(ev));
}
__global__ void k_seg_norm_init() {
    int tid = blockIdx.x * blockDim.x + threadIdx.x;
    if (tid >= N_NODES * NH) return;
    float m = dec_f(g_menc[tid]);
    g_m[tid] = m;
    float es = lrelu(g_as[tid] + g_ad[tid]);  // self-loop
    g_sum[tid] = expf(es - m);
}
__global__ void k_edge_sum(const int* __restrict__ src, const int* __restrict__ dst) {
    int tid = blockIdx.x * blockDim.x + threadIdx.x;
    if (tid >= NE * NH) return;
    int e = tid >> 1, h = tid & 1;
    int s = src[e], d = dst[e];
    float ev = lrelu(g_as[s * NH + h] + g_ad[d * NH + h]);
    atomicAdd(&g_sum[d * NH + h], expf(ev - g_m[d * NH + h]));
}
__global__ void k_gagg_self() {
    int i = blockIdx.x * blockDim.x + threadIdx.x;
    if (i >= N_NODES) return;
    float alpha[NH];
#pragma unroll
    for (int h = 0; h < NH; h++) {
        float es = lrelu(g_as[i * NH + h] + g_ad[i * NH + h]);
        alpha[h] = expf(es - g_m[i * NH + h]) / (g_sum[i * NH + h] + 1e-16f);
    }
#pragma unroll
    for (int c = 0; c < OC; c++)
        g_aggG[i * OC + c] = g_hg[i * OC + c] * alpha[c / NC];
}
__global__ void k_gagg_edge(const int* __restrict__ src, const int* __restrict__ dst) {
    int tid = blockIdx.x * blockDim.x + threadIdx.x;
    if (tid >= NE * 16) return;
    int e = tid >> 4, c = tid & 15;
    if (c >= OC) return;
    int s = src[e], d = dst[e];
    int h = (c >= NC) ? 1 : 0;
    float ev = lrelu(g_as[s * NH + h] + g_ad[d * NH + h]);
    float alpha = expf(ev - g_m[d * NH + h]) / (g_sum[d * NH + h] + 1e-16f);
    atomicAdd(&g_aggG[d * OC + c], g_hg[s * OC + c] * alpha);
}

// ---------------- output: log_softmax(aggG + bg) ----------------
__global__ void k_out(const float* __restrict__ bg, float* __restrict__ out) {
    int i = blockIdx.x * blockDim.x + threadIdx.x;
    if (i >= N_NODES) return;
    float v[OC];
    float mx = -1e30f;
#pragma unroll
    for (int c = 0; c < OC; c++) {
        v[c] = g_aggG[i * OC + c] + bg[c];
        mx = fmaxf(mx, v[c]);
    }
    float s = 0.f;
#pragma unroll
    for (int c = 0; c < OC; c++) s += expf(v[c] - mx);
    float lse = mx + logf(s);
#pragma unroll
    for (int c = 0; c < OC; c++) out[i * OC + c] = v[c] - lse;
}

// ---------------- launch ----------------
extern "C" void kernel_launch(void* const* d_in, const int* in_sizes, int n_in,
                              void* d_out, int out_size) {
    const float* x       = (const float*)d_in[0];
    const int*   ei      = (const int*)  d_in[1];
    const float* W1      = (const float*)d_in[2];
    const float* b1      = (const float*)d_in[3];
    const float* W2      = (const float*)d_in[4];
    const float* b2      = (const float*)d_in[5];
    const float* Wg      = (const float*)d_in[6];
    const float* att_src = (const float*)d_in[7];
    const float* att_dst = (const float*)d_in[8];
    const float* bg      = (const float*)d_in[9];
    float* out = (float*)d_out;

    const int* src = ei;
    const int* dst = ei + NE;

    const int T = 256;
    // degrees / normalization
    k_deg_init<<<(N_NODES + T - 1) / T, T>>>();
    k_deg_edge<<<(NE + T - 1) / T, T>>>(dst);
    k_dinv<<<(N_NODES + T - 1) / T, T>>>();

    // layer 1: transform, propagate
    k_gemm1<<<(N_NODES + 127) / 128, 256>>>(x, W1);
    k_scatter_self<<<(N_NODES * 16 + T - 1) / T, T>>>();
    k_scatter_edge<<<(NE * 16 + T - 1) / T, T>>>(src, dst);

    // layer 2: relu(agg+b1) @ W2, propagate
    k_gemm2<<<(N_NODES + 15) / 16, 256>>>(b1, W2);
    k_scatter_self<<<(N_NODES * 16 + T - 1) / T, T>>>();
    k_scatter_edge<<<(NE * 16 + T - 1) / T, T>>>(src, dst);

    // GAT head
    k_gat_transform<<<(N_NODES * 32 + T - 1) / T, T>>>(b2, Wg);
    k_node_att<<<(N_NODES * NH + T - 1) / T, T>>>(att_src, att_dst);
    k_edge_max<<<(NE * NH + T - 1) / T, T>>>(src, dst);
    k_seg_norm_init<<<(N_NODES * NH + T - 1) / T, T>>>();
    k_edge_sum<<<(NE * NH + T - 1) / T, T>>>(src, dst);
    k_gagg_self<<<(N_NODES + T - 1) / T, T>>>();
    k_gagg_edge<<<(NE * 16 + T - 1) / T, T>>>(src, dst);

    // output
    k_out<<<(N_NODES + T - 1) / T, T>>>(bg, out);
}

// round 6
// speedup vs baseline: 1.1184x; 1.1184x over previous
#include <cuda_runtime.h>
#include <mma.h>
using namespace nvcuda;

#define N_NODES 100000
#define N_PAD   100096   // 782*128, for unguarded wmma stores
#define NE      1600000
#define FIN     1433
#define HD      64
#define NH      2
#define NC      7
#define OC      14   // NH*NC

// ---------------- scratch (static device globals; no allocation) ----------------
__device__ float g_deg [N_NODES];
__device__ float g_dinv[N_NODES];
__device__ float g_bufA[N_PAD   * HD];   // transformed features (x@W1, then h1@W2)
__device__ float g_bufB[N_NODES * HD];   // aggregated features
__device__ float g_hg  [N_NODES * OC];   // GAT transformed features
__device__ float g_as  [N_NODES * NH];   // a_src per node/head
__device__ float g_ad  [N_NODES * NH];   // a_dst per node/head
__device__ int   g_menc[N_NODES * NH];   // encoded segment max
__device__ float g_m   [N_NODES * NH];   // decoded segment max
__device__ float g_sum [N_NODES * NH];   // segment softmax denominator
__device__ float g_aggG[N_NODES * OC];   // GAT aggregation

// ---------------- helpers ----------------
__device__ __forceinline__ float lrelu(float x) { return x > 0.f ? x : 0.2f * x; }
__device__ __forceinline__ int   enc_f(float f) { int i = __float_as_int(f); return i >= 0 ? i : i ^ 0x7fffffff; }
__device__ __forceinline__ float dec_f(int i)   { return __int_as_float(i >= 0 ? i : i ^ 0x7fffffff); }

// ---------------- degree / normalization ----------------
__global__ void k_deg_init() {
    int i = blockIdx.x * blockDim.x + threadIdx.x;
    if (i < N_NODES) g_deg[i] = 1.0f;  // self-loop
}
__global__ void k_deg_edge(const int* __restrict__ dst) {
    int e = blockIdx.x * blockDim.x + threadIdx.x;
    if (e < NE) atomicAdd(&g_deg[dst[e]], 1.0f);
}
__global__ void k_dinv() {
    int i = blockIdx.x * blockDim.x + threadIdx.x;
    if (i < N_NODES) g_dinv[i] = rsqrtf(g_deg[i]);
}

// ---------------- GEMM1 (TF32 tensor cores): g_bufA = x @ W1 ----------------
// 128x64 block tile, BK=16, 256 threads = 8 warps in 4(M)x2(N).
// Each warp: 32x32 via 2x2 wmma m16n16k8 tf32 fragments.
__global__ void __launch_bounds__(256) k_gemm1(const float* __restrict__ X,
                                               const float* __restrict__ W) {
    __shared__ float As[128][24];   // [m][k], ld=24 (mult of 8)
    __shared__ float Bs[16][72];    // [k][n], ld=72 (mult of 8)
    const int t    = threadIdx.x;
    const int warp = t >> 5;
    const int wm   = warp >> 1;     // 0..3 -> rows wm*32
    const int wn   = warp & 1;      // 0..1 -> cols wn*32
    const int block_row = blockIdx.x * 128;

    wmma::fragment<wmma::accumulator, 16, 16, 8, float> acc[2][2];
#pragma unroll
    for (int i = 0; i < 2; i++)
#pragma unroll
        for (int j = 0; j < 2; j++) wmma::fill_fragment(acc[i][j], 0.0f);

    for (int k0 = 0; k0 < FIN; k0 += 16) {
        // A tile: 128x16 = 2048 floats, 8 per thread, coalesced along k
#pragma unroll
        for (int i = 0; i < 8; i++) {
            int idx = i * 256 + t;
            int r = idx >> 4, k = idx & 15;
            int gr = block_row + r, gk = k0 + k;
            float v = 0.f;
            if (gr < N_NODES && gk < FIN) v = X[gr * FIN + gk];
            As[r][k] = v;
        }
        // B tile: 16x64 = 1024 floats
#pragma unroll
        for (int i = 0; i < 4; i++) {
            int idx = i * 256 + t;
            int k = idx >> 6, c = idx & 63;
            int gk = k0 + k;
            Bs[k][c] = (gk < FIN) ? W[gk * HD + c] : 0.f;
        }
        __syncthreads();
#pragma unroll
        for (int ks = 0; ks < 2; ks++) {
            wmma::fragment<wmma::matrix_a, 16, 16, 8, wmma::precision::tf32, wmma::row_major> af[2];
            wmma::fragment<wmma::matrix_b, 16, 16, 8, wmma::precision::tf32, wmma::row_major> bf[2];
#pragma unroll
            for (int i = 0; i < 2; i++) {
                wmma::load_matrix_sync(af[i], &As[wm * 32 + i * 16][ks * 8], 24);
#pragma unroll
                for (int x = 0; x < af[i].num_elements; x++)
                    af[i].x[x] = wmma::__float_to_tf32(af[i].x[x]);
            }
#pragma unroll
            for (int j = 0; j < 2; j++) {
                wmma::load_matrix_sync(bf[j], &Bs[ks * 8][wn * 32 + j * 16], 72);
#pragma unroll
                for (int x = 0; x < bf[j].num_elements; x++)
                    bf[j].x[x] = wmma::__float_to_tf32(bf[j].x[x]);
            }
#pragma unroll
            for (int i = 0; i < 2; i++)
#pragma unroll
                for (int j = 0; j < 2; j++)
                    wmma::mma_sync(acc[i][j], af[i], bf[j], acc[i][j]);
        }
        __syncthreads();
    }
    // store (g_bufA padded to N_PAD rows so the tail block stays in-bounds)
#pragma unroll
    for (int i = 0; i < 2; i++) {
        int row = block_row + wm * 32 + i * 16;
#pragma unroll
        for (int j = 0; j < 2; j++) {
            int col = wn * 32 + j * 16;
            wmma::store_matrix_sync(&g_bufA[row * HD + col], acc[i][j], HD, wmma::mem_row_major);
        }
    }
}

// ---------------- GCN propagation: bufB = scatter(bufA) ----------------
__global__ void k_scatter_self() {
    int tid = blockIdx.x * blockDim.x + threadIdx.x;
    if (tid >= N_NODES * 16) return;
    int i = tid >> 4, l = tid & 15;
    float di = g_dinv[i];
    float s = di * di;
    float4 v = ((const float4*)(g_bufA + i * HD))[l];
    v.x *= s; v.y *= s; v.z *= s; v.w *= s;
    ((float4*)(g_bufB + i * HD))[l] = v;
}
__global__ void k_scatter_edge(const int* __restrict__ src, const int* __restrict__ dst) {
    int tid = blockIdx.x * blockDim.x + threadIdx.x;
    if (tid >= NE * 16) return;
    int e = tid >> 4, l = tid & 15;
    int s = src[e], d = dst[e];
    float nrm = g_dinv[s] * g_dinv[d];
    float4 v = ((const float4*)(g_bufA + s * HD))[l];
    v.x *= nrm; v.y *= nrm; v.z *= nrm; v.w *= nrm;
    atomicAdd(((float4*)(g_bufB + d * HD)) + l, v);
}

// ---------------- GEMM2: bufA = relu(bufB + b1) @ W2   (64x64) ----------------
__global__ void __launch_bounds__(256) k_gemm2(const float* __restrict__ bias,
                                               const float* __restrict__ W) {
    __shared__ float Ws[HD * HD];
    __shared__ float As2[16][HD];
    const int t = threadIdx.x;
    const int rows = blockIdx.x * 16;
#pragma unroll
    for (int i = 0; i < 16; i++) Ws[t + i * 256] = W[t + i * 256];
#pragma unroll
    for (int i = 0; i < 4; i++) {
        int idx = t + i * 256;
        int r = idx >> 6, c = idx & 63;
        int gr = rows + r;
        float v = 0.f;
        if (gr < N_NODES) v = fmaxf(g_bufB[gr * HD + c] + bias[c], 0.f);
        As2[r][c] = v;
    }
    __syncthreads();
    int r = t >> 4, cg = t & 15;
    float acc[4] = {0.f, 0.f, 0.f, 0.f};
#pragma unroll
    for (int k = 0; k < HD; k++) {
        float a = As2[r][k];
#pragma unroll
        for (int j = 0; j < 4; j++) acc[j] += a * Ws[k * HD + cg + 16 * j];
    }
    int gr = rows + r;
    if (gr < N_NODES) {
#pragma unroll
        for (int j = 0; j < 4; j++) g_bufA[gr * HD + cg + 16 * j] = acc[j];
    }
}

// ---------------- GAT transform: hg = relu(bufB + b2) @ Wg  (64x14) ----------------
__global__ void k_gat_transform(const float* __restrict__ bias, const float* __restrict__ Wg) {
    __shared__ float Ws[HD * OC];
    int t = threadIdx.x;
    for (int idx = t; idx < HD * OC; idx += blockDim.x) Ws[idx] = Wg[idx];
    __syncthreads();
    int node = (blockIdx.x * blockDim.x + t) >> 5;
    int lane = t & 31;
    if (node >= N_NODES) return;
    float f_lo = fmaxf(g_bufB[node * HD + lane]      + bias[lane],      0.f);
    float f_hi = fmaxf(g_bufB[node * HD + 32 + lane] + bias[32 + lane], 0.f);
    int c = lane < OC ? lane : 0;
    float acc = 0.f;
#pragma unroll
    for (int k = 0; k < 32; k++) {
        float a = __shfl_sync(0xffffffffu, f_lo, k);
        acc += a * Ws[k * OC + c];
    }
#pragma unroll
    for (int k = 0; k < 32; k++) {
        float a = __shfl_sync(0xffffffffu, f_hi, k);
        acc += a * Ws[(k + 32) * OC + c];
    }
    if (lane < OC) g_hg[node * OC + lane] = acc;
}

// ---------------- attention scalars + max init (self-loop) ----------------
__global__ void k_node_att(const float* __restrict__ att_src, const float* __restrict__ att_dst) {
    int tid = blockIdx.x * blockDim.x + threadIdx.x;
    if (tid >= N_NODES * NH) return;
    int i = tid >> 1, h = tid & 1;
    const float* hrow = g_hg + i * OC + h * NC;
    float as = 0.f, ad = 0.f;
#pragma unroll
    for (int c = 0; c < NC; c++) {
        as += hrow[c] * att_src[h * NC + c];
        ad += hrow[c] * att_dst[h * NC + c];
    }
    g_as[tid] = as;
    g_ad[tid] = ad;
    g_menc[tid] = enc_f(lrelu(as + ad));   // self-loop seeds segment max
}
__global__ void k_edge_max(const int* __restrict__ src, const int* __restrict__ dst) {
    int tid = blockIdx.x * blockDim.x + threadIdx.x;
    if (tid >= NE * NH) return;
    int e = tid >> 1, h = tid & 1;
    int s = src[e], d = dst[e];
    float ev = lrelu(g_as[s * NH + h] + g_ad[d * NH + h]);
    atomicMax(&g_menc[d * NH + h], enc_f(ev));
}
__global__ void k_seg_norm_init() {
    int tid = blockIdx.x * blockDim.x + threadIdx.x;
    if (tid >= N_NODES * NH) return;
    float m = dec_f(g_menc[tid]);
    g_m[tid] = m;
    float es = lrelu(g_as[tid] + g_ad[tid]);  // self-loop
    g_sum[tid] = expf(es - m);
}
__global__ void k_edge_sum(const int* __restrict__ src, const int* __restrict__ dst) {
    int tid = blockIdx.x * blockDim.x + threadIdx.x;
    if (tid >= NE * NH) return;
    int e = tid >> 1, h = tid & 1;
    int s = src[e], d = dst[e];
    float ev = lrelu(g_as[s * NH + h] + g_ad[d * NH + h]);
    atomicAdd(&g_sum[d * NH + h], expf(ev - g_m[d * NH + h]));
}
__global__ void k_gagg_self() {
    int i = blockIdx.x * blockDim.x + threadIdx.x;
    if (i >= N_NODES) return;
    float alpha[NH];
#pragma unroll
    for (int h = 0; h < NH; h++) {
        float es = lrelu(g_as[i * NH + h] + g_ad[i * NH + h]);
        alpha[h] = expf(es - g_m[i * NH + h]) / (g_sum[i * NH + h] + 1e-16f);
    }
#pragma unroll
    for (int c = 0; c < OC; c++)
        g_aggG[i * OC + c] = g_hg[i * OC + c] * alpha[c / NC];
}
__global__ void k_gagg_edge(const int* __restrict__ src, const int* __restrict__ dst) {
    int tid = blockIdx.x * blockDim.x + threadIdx.x;
    if (tid >= NE * 16) return;
    int e = tid >> 4, c = tid & 15;
    if (c >= OC) return;
    int s = src[e], d = dst[e];
    int h = (c >= NC) ? 1 : 0;
    float ev = lrelu(g_as[s * NH + h] + g_ad[d * NH + h]);
    float alpha = expf(ev - g_m[d * NH + h]) / (g_sum[d * NH + h] + 1e-16f);
    atomicAdd(&g_aggG[d * OC + c], g_hg[s * OC + c] * alpha);
}

// ---------------- output: log_softmax(aggG + bg) ----------------
__global__ void k_out(const float* __restrict__ bg, float* __restrict__ out) {
    int i = blockIdx.x * blockDim.x + threadIdx.x;
    if (i >= N_NODES) return;
    float v[OC];
    float mx = -1e30f;
#pragma unroll
    for (int c = 0; c < OC; c++) {
        v[c] = g_aggG[i * OC + c] + bg[c];
        mx = fmaxf(mx, v[c]);
    }
    float s = 0.f;
#pragma unroll
    for (int c = 0; c < OC; c++) s += expf(v[c] - mx);
    float lse = mx + logf(s);
#pragma unroll
    for (int c = 0; c < OC; c++) out[i * OC + c] = v[c] - lse;
}

// ---------------- launch ----------------
extern "C" void kernel_launch(void* const* d_in, const int* in_sizes, int n_in,
                              void* d_out, int out_size) {
    const float* x       = (const float*)d_in[0];
    const int*   ei      = (const int*)  d_in[1];
    const float* W1      = (const float*)d_in[2];
    const float* b1      = (const float*)d_in[3];
    const float* W2      = (const float*)d_in[4];
    const float* b2      = (const float*)d_in[5];
    const float* Wg      = (const float*)d_in[6];
    const float* att_src = (const float*)d_in[7];
    const float* att_dst = (const float*)d_in[8];
    const float* bg      = (const float*)d_in[9];
    float* out = (float*)d_out;

    const int* src = ei;
    const int* dst = ei + NE;

    const int T = 256;
    // degrees / normalization
    k_deg_init<<<(N_NODES + T - 1) / T, T>>>();
    k_deg_edge<<<(NE + T - 1) / T, T>>>(dst);
    k_dinv<<<(N_NODES + T - 1) / T, T>>>();

    // layer 1: transform (tensor cores), propagate
    k_gemm1<<<(N_NODES + 127) / 128, 256>>>(x, W1);
    k_scatter_self<<<(N_NODES * 16 + T - 1) / T, T>>>();
    k_scatter_edge<<<(NE * 16 + T - 1) / T, T>>>(src, dst);

    // layer 2: relu(agg+b1) @ W2, propagate
    k_gemm2<<<(N_NODES + 15) / 16, 256>>>(b1, W2);
    k_scatter_self<<<(N_NODES * 16 + T - 1) / T, T>>>();
    k_scatter_edge<<<(NE * 16 + T - 1) / T, T>>>(src, dst);

    // GAT head
    k_gat_transform<<<(N_NODES * 32 + T - 1) / T, T>>>(b2, Wg);
    k_node_att<<<(N_NODES * NH + T - 1) / T, T>>>(att_src, att_dst);
    k_edge_max<<<(NE * NH + T - 1) / T, T>>>(src, dst);
    k_seg_norm_init<<<(N_NODES * NH + T - 1) / T, T>>>();
    k_edge_sum<<<(NE * NH + T - 1) / T, T>>>(src, dst);
    k_gagg_self<<<(N_NODES + T - 1) / T, T>>>();
    k_gagg_edge<<<(NE * 16 + T - 1) / T, T>>>(src, dst);

    // output
    k_out<<<(N_NODES + T - 1) / T, T>>>(bg, out);
}

// round 10
// speedup vs baseline: 1.2640x; 1.1301x over previous
#include <cuda_runtime.h>
#include <cstdint>
#include <mma.h>
using namespace nvcuda;

#define N_NODES 100000
#define N_PAD   100096   // 782*128, for unguarded wmma stores
#define NE      1600000
#define FIN     1433
#define HD      64
#define NH      2
#define NC      7
#define OC      14   // NH*NC

// ---------------- scratch (static device globals; no allocation) ----------------
__device__ float g_deg [N_NODES];
__device__ float g_dinv[N_NODES];
__device__ float g_bufA[N_PAD   * HD];   // transformed features (x@W1, then h1@W2)
__device__ float g_bufB[N_NODES * HD];   // aggregated features
__device__ float g_hg  [N_NODES * OC];   // GAT transformed features
__device__ float g_as  [N_NODES * NH];   // a_src per node/head
__device__ float g_ad  [N_NODES * NH];   // a_dst per node/head
__device__ int   g_menc[N_NODES * NH];   // encoded segment max
__device__ float g_m   [N_NODES * NH];   // decoded segment max
__device__ float g_sum [N_NODES * NH];   // segment softmax denominator
__device__ float g_aggG[N_NODES * OC];   // GAT aggregation

// ---------------- helpers ----------------
__device__ __forceinline__ float lrelu(float x) { return x > 0.f ? x : 0.2f * x; }
__device__ __forceinline__ int   enc_f(float f) { int i = __float_as_int(f); return i >= 0 ? i : i ^ 0x7fffffff; }
__device__ __forceinline__ float dec_f(int i)   { return __int_as_float(i >= 0 ? i : i ^ 0x7fffffff); }

// cp.async: src_size=0 zero-fills the destination (branch-free OOB handling)
__device__ __forceinline__ void cp_async4(void* smem, const void* gmem, bool pred) {
    unsigned int s = (unsigned int)__cvta_generic_to_shared(smem);
    int sz = pred ? 4 : 0;
    asm volatile("cp.async.ca.shared.global [%0], [%1], 4, %2;" :: "r"(s), "l"(gmem), "r"(sz));
}
__device__ __forceinline__ void cp_async16(void* smem, const void* gmem, bool pred) {
    unsigned int s = (unsigned int)__cvta_generic_to_shared(smem);
    int sz = pred ? 16 : 0;
    asm volatile("cp.async.cg.shared.global [%0], [%1], 16, %2;" :: "r"(s), "l"(gmem), "r"(sz));
}

// ---------------- degree / normalization ----------------
__global__ void k_deg_init() {
    int i = blockIdx.x * blockDim.x + threadIdx.x;
    if (i < N_NODES) g_deg[i] = 1.0f;  // self-loop
}
__global__ void k_deg_edge(const int* __restrict__ dst) {
    int e = blockIdx.x * blockDim.x + threadIdx.x;
    if (e < NE) atomicAdd(&g_deg[dst[e]], 1.0f);
}
__global__ void k_dinv() {
    int i = blockIdx.x * blockDim.x + threadIdx.x;
    if (i < N_NODES) g_dinv[i] = rsqrtf(g_deg[i]);
}

// ---------------- GEMM1 (TF32 tensor cores + cp.async pipeline): g_bufA = x @ W1 ----------------
// 128x64 block tile, BK=16, double-buffered smem, 256 threads = 8 warps in 4(M)x2(N).
__global__ void __launch_bounds__(256) k_gemm1(const float* __restrict__ X,
                                               const float* __restrict__ W) {
    __shared__ __align__(16) float As[2][128][24];   // [buf][m][k], ld=24
    __shared__ __align__(16) float Bs[2][16][72];    // [buf][k][n], ld=72
    const int t    = threadIdx.x;
    const int warp = t >> 5;
    const int wm   = warp >> 1;     // 0..3 -> rows wm*32
    const int wn   = warp & 1;      // 0..1 -> cols wn*32
    const int block_row = blockIdx.x * 128;

    wmma::fragment<wmma::accumulator, 16, 16, 8, float> acc[2][2];
#pragma unroll
    for (int i = 0; i < 2; i++)
#pragma unroll
        for (int j = 0; j < 2; j++) wmma::fill_fragment(acc[i][j], 0.0f);

    // per-thread load descriptors
    const int ar = t >> 4;          // base A row group: rows ar, ar+16, ... (8 rows/thread)
    const int ak = t & 15;          // A k within tile
    const int brow = t >> 4;        // B row (0..15)
    const int bc4  = t & 15;        // B 16B chunk (4 cols)

    const int KT = (FIN + 15) / 16; // 90 (last tile has 9 valid k)

    // ---- prologue: prefetch tile 0 ----
    {
#pragma unroll
        for (int i = 0; i < 8; i++) {
            int r = ar + i * 16;
            int gr = block_row + r;
            bool p = (gr < N_NODES) && (ak < FIN);
            cp_async4(&As[0][r][ak], X + (size_t)gr * FIN + ak, p);
        }
        cp_async16(&Bs[0][brow][bc4 * 4], W + brow * HD + bc4 * 4, brow < FIN);
        asm volatile("cp.async.commit_group;");
    }

    for (int kt = 0; kt < KT; kt++) {
        const int cur = kt & 1;
        if (kt + 1 < KT) {
            const int nk0 = (kt + 1) * 16;
            const int nxt = cur ^ 1;
#pragma unroll
            for (int i = 0; i < 8; i++) {
                int r = ar + i * 16;
                int gr = block_row + r, gk = nk0 + ak;
                bool p = (gr < N_NODES) && (gk < FIN);
                cp_async4(&As[nxt][r][ak], X + (size_t)gr * FIN + gk, p);
            }
            {
                int gk = nk0 + brow;
                cp_async16(&Bs[nxt][brow][bc4 * 4], W + gk * HD + bc4 * 4, gk < FIN);
            }
            asm volatile("cp.async.commit_group;");
            asm volatile("cp.async.wait_group 1;");
        } else {
            asm volatile("cp.async.wait_group 0;");
        }
        __syncthreads();

#pragma unroll
        for (int ks = 0; ks < 2; ks++) {
            wmma::fragment<wmma::matrix_a, 16, 16, 8, wmma::precision::tf32, wmma::row_major> af[2];
            wmma::fragment<wmma::matrix_b, 16, 16, 8, wmma::precision::tf32, wmma::row_major> bf[2];
#pragma unroll
            for (int i = 0; i < 2; i++) {
                wmma::load_matrix_sync(af[i], &As[cur][wm * 32 + i * 16][ks * 8], 24);
#pragma unroll
                for (int x = 0; x < af[i].num_elements; x++)
                    af[i].x[x] = wmma::__float_to_tf32(af[i].x[x]);
            }
#pragma unroll
            for (int j = 0; j < 2; j++) {
                wmma::load_matrix_sync(bf[j], &Bs[cur][ks * 8][wn * 32 + j * 16], 72);
#pragma unroll
                for (int x = 0; x < bf[j].num_elements; x++)
                    bf[j].x[x] = wmma::__float_to_tf32(bf[j].x[x]);
            }
#pragma unroll
            for (int i = 0; i < 2; i++)
#pragma unroll
                for (int j = 0; j < 2; j++)
                    wmma::mma_sync(acc[i][j], af[i], bf[j], acc[i][j]);
        }
        __syncthreads();
    }

    // store (g_bufA padded to N_PAD rows so the tail block stays in-bounds)
#pragma unroll
    for (int i = 0; i < 2; i++) {
        int row = block_row + wm * 32 + i * 16;
#pragma unroll
        for (int j = 0; j < 2; j++) {
            int col = wn * 32 + j * 16;
            wmma::store_matrix_sync(&g_bufA[row * HD + col], acc[i][j], HD, wmma::mem_row_major);
        }
    }
}

// ---------------- GCN propagation: bufB = scatter(bufA) ----------------
__global__ void k_scatter_self() {
    int tid = blockIdx.x * blockDim.x + threadIdx.x;
    if (tid >= N_NODES * 16) return;
    int i = tid >> 4, l = tid & 15;
    float di = g_dinv[i];
    float s = di * di;
    float4 v = ((const float4*)(g_bufA + i * HD))[l];
    v.x *= s; v.y *= s; v.z *= s; v.w *= s;
    ((float4*)(g_bufB + i * HD))[l] = v;
}
__global__ void k_scatter_edge(const int* __restrict__ src, const int* __restrict__ dst) {
    int tid = blockIdx.x * blockDim.x + threadIdx.x;
    if (tid >= NE * 16) return;
    int e = tid >> 4, l = tid & 15;
    int s = src[e], d = dst[e];
    float nrm = g_dinv[s] * g_dinv[d];
    float4 v = ((const float4*)(g_bufA + s * HD))[l];
    v.x *= nrm; v.y *= nrm; v.z *= nrm; v.w *= nrm;
    atomicAdd(((float4*)(g_bufB + d * HD)) + l, v);
}

// ---------------- GEMM2: bufA = relu(bufB + b1) @ W2   (64x64) ----------------
__global__ void __launch_bounds__(256) k_gemm2(const float* __restrict__ bias,
                                               const float* __restrict__ W) {
    __shared__ float Ws[HD * HD];
    __shared__ float As2[16][HD];
    const int t = threadIdx.x;
    const int rows = blockIdx.x * 16;
#pragma unroll
    for (int i = 0; i < 16; i++) Ws[t + i * 256] = W[t + i * 256];
#pragma unroll
    for (int i = 0; i < 4; i++) {
        int idx = t + i * 256;
        int r = idx >> 6, c = idx & 63;
        int gr = rows + r;
        float v = 0.f;
        if (gr < N_NODES) v = fmaxf(g_bufB[gr * HD + c] + bias[c], 0.f);
        As2[r][c] = v;
    }
    __syncthreads();
    int r = t >> 4, cg = t & 15;
    float acc[4] = {0.f, 0.f, 0.f, 0.f};
#pragma unroll
    for (int k = 0; k < HD; k++) {
        float a = As2[r][k];
#pragma unroll
        for (int j = 0; j < 4; j++) acc[j] += a * Ws[k * HD + cg + 16 * j];
    }
    int gr = rows + r;
    if (gr < N_NODES) {
#pragma unroll
        for (int j = 0; j < 4; j++) g_bufA[gr * HD + cg + 16 * j] = acc[j];
    }
}

// ---------------- GAT transform: hg = relu(bufB + b2) @ Wg  (64x14) ----------------
__global__ void k_gat_transform(const float* __restrict__ bias, const float* __restrict__ Wg) {
    __shared__ float Ws[HD * OC];
    int t = threadIdx.x;
    for (int idx = t; idx < HD * OC; idx += blockDim.x) Ws[idx] = Wg[idx];
    __syncthreads();
    int node = (blockIdx.x * blockDim.x + t) >> 5;
    int lane = t & 31;
    if (node >= N_NODES) return;
    float f_lo = fmaxf(g_bufB[node * HD + lane]      + bias[lane],      0.f);
    float f_hi = fmaxf(g_bufB[node * HD + 32 + lane] + bias[32 + lane], 0.f);
    int c = lane < OC ? lane : 0;
    float acc = 0.f;
#pragma unroll
    for (int k = 0; k < 32; k++) {
        float a = __shfl_sync(0xffffffffu, f_lo, k);
        acc += a * Ws[k * OC + c];
    }
#pragma unroll
    for (int k = 0; k < 32; k++) {
        float a = __shfl_sync(0xffffffffu, f_hi, k);
        acc += a * Ws[(k + 32) * OC + c];
    }
    if (lane < OC) g_hg[node * OC + lane] = acc;
}

// ---------------- attention scalars + max init (self-loop) ----------------
__global__ void k_node_att(const float* __restrict__ att_src, const float* __restrict__ att_dst) {
    int tid = blockIdx.x * blockDim.x + threadIdx.x;
    if (tid >= N_NODES * NH) return;
    int i = tid >> 1, h = tid & 1;
    const float* hrow = g_hg + i * OC + h * NC;
    float as = 0.f, ad = 0.f;
#pragma unroll
    for (int c = 0; c < NC; c++) {
        as += hrow[c] * att_src[h * NC + c];
        ad += hrow[c] * att_dst[h * NC + c];
    }
    g_as[tid] = as;
    g_ad[tid] = ad;
    g_menc[tid] = enc_f(lrelu(as + ad));   // self-loop seeds segment max
}
__global__ void k_edge_max(const int* __restrict__ src, const int* __restrict__ dst) {
    int tid = blockIdx.x * blockDim.x + threadIdx.x;
    if (tid >= NE * NH) return;
    int e = tid >> 1, h = tid & 1;
    int s = src[e], d = dst[e];
    float ev = lrelu(g_as[s * NH + h] + g_ad[d * NH + h]);
    atomicMax(&g_menc[d * NH + h], enc_f(ev));
}
__global__ void k_seg_norm_init() {
    int tid = blockIdx.x * blockDim.x + threadIdx.x;
    if (tid >= N_NODES * NH) return;
    float m = dec_f(g_menc[tid]);
    g_m[tid] = m;
    float es = lrelu(g_as[tid] + g_ad[tid]);  // self-loop
    g_sum[tid] = expf(es - m);
}
__global__ void k_edge_sum(const int* __restrict__ src, const int* __restrict__ dst) {
    int tid = blockIdx.x * blockDim.x + threadIdx.x;
    if (tid >= NE * NH) return;
    int e = tid >> 1, h = tid & 1;
    int s = src[e], d = dst[e];
    float ev = lrelu(g_as[s * NH + h] + g_ad[d * NH + h]);
    atomicAdd(&g_sum[d * NH + h], expf(ev - g_m[d * NH + h]));
}
__global__ void k_gagg_self() {
    int i = blockIdx.x * blockDim.x + threadIdx.x;
    if (i >= N_NODES) return;
    float alpha[NH];
#pragma unroll
    for (int h = 0; h < NH; h++) {
        float es = lrelu(g_as[i * NH + h] + g_ad[i * NH + h]);
        alpha[h] = expf(es - g_m[i * NH + h]) / (g_sum[i * NH + h] + 1e-16f);
    }
#pragma unroll
    for (int c = 0; c < OC; c++)
        g_aggG[i * OC + c] = g_hg[i * OC + c] * alpha[c / NC];
}
__global__ void k_gagg_edge(const int* __restrict__ src, const int* __restrict__ dst) {
    int tid = blockIdx.x * blockDim.x + threadIdx.x;
    if (tid >= NE * 16) return;
    int e = tid >> 4, c = tid & 15;
    if (c >= OC) return;
    int s = src[e], d = dst[e];
    int h = (c >= NC) ? 1 : 0;
    float ev = lrelu(g_as[s * NH + h] + g_ad[d * NH + h]);
    float alpha = expf(ev - g_m[d * NH + h]) / (g_sum[d * NH + h] + 1e-16f);
    atomicAdd(&g_aggG[d * OC + c], g_hg[s * OC + c] * alpha);
}

// ---------------- output: log_softmax(aggG + bg) ----------------
__global__ void k_out(const float* __restrict__ bg, float* __restrict__ out) {
    int i = blockIdx.x * blockDim.x + threadIdx.x;
    if (i >= N_NODES) return;
    float v[OC];
    float mx = -1e30f;
#pragma unroll
    for (int c = 0; c < OC; c++) {
        v[c] = g_aggG[i * OC + c] + bg[c];
        mx = fmaxf(mx, v[c]);
    }
    float s = 0.f;
#pragma unroll
    for (int c = 0; c < OC; c++) s += expf(v[c] - mx);
    float lse = mx + logf(s);
#pragma unroll
    for (int c = 0; c < OC; c++) out[i * OC + c] = v[c] - lse;
}

// ---------------- launch ----------------
extern "C" void kernel_launch(void* const* d_in, const int* in_sizes, int n_in,
                              void* d_out, int out_size) {
    const float* x       = (const float*)d_in[0];
    const int*   ei      = (const int*)  d_in[1];
    const float* W1      = (const float*)d_in[2];
    const float* b1      = (const float*)d_in[3];
    const float* W2      = (const float*)d_in[4];
    const float* b2      = (const float*)d_in[5];
    const float* Wg      = (const float*)d_in[6];
    const float* att_src = (const float*)d_in[7];
    const float* att_dst = (const float*)d_in[8];
    const float* bg      = (const float*)d_in[9];
    float* out = (float*)d_out;

    const int* src = ei;
    const int* dst = ei + NE;

    const int T = 256;
    // degrees / normalization
    k_deg_init<<<(N_NODES + T - 1) / T, T>>>();
    k_deg_edge<<<(NE + T - 1) / T, T>>>(dst);
    k_dinv<<<(N_NODES + T - 1) / T, T>>>();

    // layer 1: transform (tensor cores + cp.async pipeline), propagate
    k_gemm1<<<(N_NODES + 127) / 128, 256>>>(x, W1);
    k_scatter_self<<<(N_NODES * 16 + T - 1) / T, T>>>();
    k_scatter_edge<<<(NE * 16 + T - 1) / T, T>>>(src, dst);

    // layer 2: relu(agg+b1) @ W2, propagate
    k_gemm2<<<(N_NODES + 15) / 16, 256>>>(b1, W2);
    k_scatter_self<<<(N_NODES * 16 + T - 1) / T, T>>>();
    k_scatter_edge<<<(NE * 16 + T - 1) / T, T>>>(src, dst);

    // GAT head
    k_gat_transform<<<(N_NODES * 32 + T - 1) / T, T>>>(b2, Wg);
    k_node_att<<<(N_NODES * NH + T - 1) / T, T>>>(att_src, att_dst);
    k_edge_max<<<(NE * NH + T - 1) / T, T>>>(src, dst);
    k_seg_norm_init<<<(N_NODES * NH + T - 1) / T, T>>>();
    k_edge_sum<<<(NE * NH + T - 1) / T, T>>>(src, dst);
    k_gagg_self<<<(N_NODES + T - 1) / T, T>>>();
    k_gagg_edge<<<(NE * 16 + T - 1) / T, T>>>(src, dst);

    // output
    k_out<<<(N_NODES + T - 1) / T, T>>>(bg, out);
}

// round 13
// speedup vs baseline: 1.2760x; 1.0095x over previous
#include <cuda_runtime.h>
#include <cstdint>
#include <mma.h>
using namespace nvcuda;

#define N_NODES 100000
#define N_PAD   100096   // 782*128, for unguarded wmma stores
#define NE      1600000
#define FIN     1433
#define HD      64
#define NH      2
#define NC      7
#define OC      14   // NH*NC

// ---------------- scratch (static device globals; no allocation) ----------------
__device__ float g_deg [N_NODES];
__device__ float g_dinv[N_NODES];
__device__ float g_bufA[N_PAD   * HD];   // transformed features (x@W1, then h1@W2)
__device__ float g_bufB[N_NODES * HD];   // aggregated features
__device__ float g_hg  [N_NODES * OC];   // GAT transformed features
__device__ float g_as  [N_NODES * NH];   // a_src per node/head
__device__ float g_ad  [N_NODES * NH];   // a_dst per node/head
__device__ int   g_menc[N_NODES * NH];   // encoded segment max
__device__ float g_m   [N_NODES * NH];   // decoded segment max
__device__ float g_sum [N_NODES * NH];   // segment softmax denominator
__device__ float g_aggG[N_NODES * OC];   // GAT aggregation

// ---------------- helpers ----------------
__device__ __forceinline__ float lrelu(float x) { return x > 0.f ? x : 0.2f * x; }
__device__ __forceinline__ int   enc_f(float f) { int i = __float_as_int(f); return i >= 0 ? i : i ^ 0x7fffffff; }
__device__ __forceinline__ float dec_f(int i)   { return __int_as_float(i >= 0 ? i : i ^ 0x7fffffff); }

// cp.async: src_size=0 zero-fills the destination (branch-free OOB handling)
__device__ __forceinline__ void cp_async4(void* smem, const void* gmem, bool pred) {
    unsigned int s = (unsigned int)__cvta_generic_to_shared(smem);
    int sz = pred ? 4 : 0;
    asm volatile("cp.async.ca.shared.global [%0], [%1], 4, %2;" :: "r"(s), "l"(gmem), "r"(sz));
}
__device__ __forceinline__ void cp_async16(void* smem, const void* gmem, bool pred) {
    unsigned int s = (unsigned int)__cvta_generic_to_shared(smem);
    int sz = pred ? 16 : 0;
    asm volatile("cp.async.cg.shared.global [%0], [%1], 16, %2;" :: "r"(s), "l"(gmem), "r"(sz));
}

// ---------------- degree / normalization ----------------
__global__ void k_deg_init() {
    int i = blockIdx.x * blockDim.x + threadIdx.x;
    if (i < N_NODES) g_deg[i] = 1.0f;  // self-loop
}
__global__ void k_deg_edge(const int* __restrict__ dst) {
    int e = blockIdx.x * blockDim.x + threadIdx.x;
    if (e < NE) atomicAdd(&g_deg[dst[e]], 1.0f);
}
__global__ void k_dinv() {
    int i = blockIdx.x * blockDim.x + threadIdx.x;
    if (i < N_NODES) g_dinv[i] = rsqrtf(g_deg[i]);
}

// ---------------- GEMM1 (TF32 tensor cores, 3-stage cp.async, distance-2): g_bufA = x @ W1 ----
// 128x64 block tile, BK=16, 256 threads = 8 warps in 4(M)x2(N), each warp 32x32.
// A stored col-major in smem ([k][m], ld=136) -> conflict-free fragment LDS, smaller stage.
// fp32 bits fed directly to tf32 MMA (truncation; no per-element convert).
#define KT_TILES ((FIN + 15) / 16)   // 90
__global__ void __launch_bounds__(256) k_gemm1(const float* __restrict__ X,
                                               const float* __restrict__ W) {
    __shared__ __align__(16) float As[3][16][136];   // [stage][k][m], ld=136
    __shared__ __align__(16) float Bs[3][16][72];    // [stage][k][n], ld=72
    const int t    = threadIdx.x;
    const int warp = t >> 5;
    const int wm   = warp >> 1;     // 0..3 -> rows wm*32
    const int wn   = warp & 1;      // 0..1 -> cols wn*32
    const int block_row = blockIdx.x * 128;

    wmma::fragment<wmma::accumulator, 16, 16, 8, float> acc[2][2];
#pragma unroll
    for (int i = 0; i < 2; i++)
#pragma unroll
        for (int j = 0; j < 2; j++) wmma::fill_fragment(acc[i][j], 0.0f);

    // per-thread load descriptors (gmem-coalesced: 16 consecutive k per row-group)
    const int ar = t >> 4;          // base A row: rows ar, ar+16, ... (8 rows/thread)
    const int ak = t & 15;          // A k within tile
    const int brow = t >> 4;        // B row (0..15)
    const int bc4  = t & 15;        // B 16B chunk (4 cols)

    const bool rowok[1] = {true};   // (row guards inline below)

    // ---- prologue: prefetch tiles 0 and 1 ----
#pragma unroll
    for (int pt = 0; pt < 2; pt++) {
        const int k0 = pt * 16;
#pragma unroll
        for (int i = 0; i < 8; i++) {
            int r = ar + i * 16;
            int gr = block_row + r;
            bool p = (gr < N_NODES);
            cp_async4(&As[pt][ak][r], X + (size_t)gr * FIN + k0 + ak, p);
        }
        cp_async16(&Bs[pt][brow][bc4 * 4], W + (k0 + brow) * HD + bc4 * 4, true);
        asm volatile("cp.async.commit_group;");
    }
    (void)rowok;

    for (int kt = 0; kt < KT_TILES; kt++) {
        const int cur = kt % 3;
        if (kt + 2 < KT_TILES) {
            const int nk0 = (kt + 2) * 16;
            const int nxt = (kt + 2) % 3;
#pragma unroll
            for (int i = 0; i < 8; i++) {
                int r = ar + i * 16;
                int gr = block_row + r, gk = nk0 + ak;
                bool p = (gr < N_NODES) && (gk < FIN);
                cp_async4(&As[nxt][ak][r], X + (size_t)gr * FIN + gk, p);
            }
            {
                int gk = nk0 + brow;
                cp_async16(&Bs[nxt][brow][bc4 * 4], W + gk * HD + bc4 * 4, gk < FIN);
            }
            asm volatile("cp.async.commit_group;");
            asm volatile("cp.async.wait_group 2;");
        } else {
            asm volatile("cp.async.wait_group 0;");
        }
        __syncthreads();

#pragma unroll
        for (int ks = 0; ks < 2; ks++) {
            // A col-major: element (m, k) at As[cur][k][m] = base[m + k*136]
            wmma::fragment<wmma::matrix_a, 16, 16, 8, wmma::precision::tf32, wmma::col_major> af[2];
            wmma::fragment<wmma::matrix_b, 16, 16, 8, wmma::precision::tf32, wmma::row_major> bf[2];
#pragma unroll
            for (int i = 0; i < 2; i++)
                wmma::load_matrix_sync(af[i], &As[cur][ks * 8][wm * 32 + i * 16], 136);
#pragma unroll
            for (int j = 0; j < 2; j++)
                wmma::load_matrix_sync(bf[j], &Bs[cur][ks * 8][wn * 32 + j * 16], 72);
            // fp32 bits used as tf32 directly (HW truncates mantissa)
#pragma unroll
            for (int i = 0; i < 2; i++)
#pragma unroll
                for (int j = 0; j < 2; j++)
                    wmma::mma_sync(acc[i][j], af[i], bf[j], acc[i][j]);
        }
        __syncthreads();
    }

    // store (g_bufA padded to N_PAD rows so the tail block stays in-bounds)
#pragma unroll
    for (int i = 0; i < 2; i++) {
        int row = block_row + wm * 32 + i * 16;
#pragma unroll
        for (int j = 0; j < 2; j++) {
            int col = wn * 32 + j * 16;
            wmma::store_matrix_sync(&g_bufA[row * HD + col], acc[i][j], HD, wmma::mem_row_major);
        }
    }
}

// ---------------- GCN propagation: bufB = scatter(bufA) ----------------
__global__ void k_scatter_self() {
    int tid = blockIdx.x * blockDim.x + threadIdx.x;
    if (tid >= N_NODES * 16) return;
    int i = tid >> 4, l = tid & 15;
    float di = g_dinv[i];
    float s = di * di;
    float4 v = ((const float4*)(g_bufA + i * HD))[l];
    v.x *= s; v.y *= s; v.z *= s; v.w *= s;
    ((float4*)(g_bufB + i * HD))[l] = v;
}
__global__ void k_scatter_edge(const int* __restrict__ src, const int* __restrict__ dst) {
    int tid = blockIdx.x * blockDim.x + threadIdx.x;
    if (tid >= NE * 16) return;
    int e = tid >> 4, l = tid & 15;
    int s = src[e], d = dst[e];
    float nrm = g_dinv[s] * g_dinv[d];
    float4 v = ((const float4*)(g_bufA + s * HD))[l];
    v.x *= nrm; v.y *= nrm; v.z *= nrm; v.w *= nrm;
    atomicAdd(((float4*)(g_bufB + d * HD)) + l, v);
}

// ---------------- GEMM2: bufA = relu(bufB + b1) @ W2   (64x64) ----------------
__global__ void __launch_bounds__(256) k_gemm2(const float* __restrict__ bias,
                                               const float* __restrict__ W) {
    __shared__ float Ws[HD * HD];
    __shared__ float As2[16][HD];
    const int t = threadIdx.x;
    const int rows = blockIdx.x * 16;
#pragma unroll
    for (int i = 0; i < 16; i++) Ws[t + i * 256] = W[t + i * 256];
#pragma unroll
    for (int i = 0; i < 4; i++) {
        int idx = t + i * 256;
        int r = idx >> 6, c = idx & 63;
        int gr = rows + r;
        float v = 0.f;
        if (gr < N_NODES) v = fmaxf(g_bufB[gr * HD + c] + bias[c], 0.f);
        As2[r][c] = v;
    }
    __syncthreads();
    int r = t >> 4, cg = t & 15;
    float acc[4] = {0.f, 0.f, 0.f, 0.f};
#pragma unroll
    for (int k = 0; k < HD; k++) {
        float a = As2[r][k];
#pragma unroll
        for (int j = 0; j < 4; j++) acc[j] += a * Ws[k * HD + cg + 16 * j];
    }
    int gr = rows + r;
    if (gr < N_NODES) {
#pragma unroll
        for (int j = 0; j < 4; j++) g_bufA[gr * HD + cg + 16 * j] = acc[j];
    }
}

// ---------------- GAT transform: hg = relu(bufB + b2) @ Wg  (64x14) ----------------
__global__ void k_gat_transform(const float* __restrict__ bias, const float* __restrict__ Wg) {
    __shared__ float Ws[HD * OC];
    int t = threadIdx.x;
    for (int idx = t; idx < HD * OC; idx += blockDim.x) Ws[idx] = Wg[idx];
    __syncthreads();
    int node = (blockIdx.x * blockDim.x + t) >> 5;
    int lane = t & 31;
    if (node >= N_NODES) return;
    float f_lo = fmaxf(g_bufB[node * HD + lane]      + bias[lane],      0.f);
    float f_hi = fmaxf(g_bufB[node * HD + 32 + lane] + bias[32 + lane], 0.f);
    int c = lane < OC ? lane : 0;
    float acc = 0.f;
#pragma unroll
    for (int k = 0; k < 32; k++) {
        float a = __shfl_sync(0xffffffffu, f_lo, k);
        acc += a * Ws[k * OC + c];
    }
#pragma unroll
    for (int k = 0; k < 32; k++) {
        float a = __shfl_sync(0xffffffffu, f_hi, k);
        acc += a * Ws[(k + 32) * OC + c];
    }
    if (lane < OC) g_hg[node * OC + lane] = acc;
}

// ---------------- attention scalars + max init (self-loop) ----------------
__global__ void k_node_att(const float* __restrict__ att_src, const float* __restrict__ att_dst) {
    int tid = blockIdx.x * blockDim.x + threadIdx.x;
    if (tid >= N_NODES * NH) return;
    int i = tid >> 1, h = tid & 1;
    const float* hrow = g_hg + i * OC + h * NC;
    float as = 0.f, ad = 0.f;
#pragma unroll
    for (int c = 0; c < NC; c++) {
        as += hrow[c] * att_src[h * NC + c];
        ad += hrow[c] * att_dst[h * NC + c];
    }
    g_as[tid] = as;
    g_ad[tid] = ad;
    g_menc[tid] = enc_f(lrelu(as + ad));   // self-loop seeds segment max
}
__global__ void k_edge_max(const int* __restrict__ src, const int* __restrict__ dst) {
    int tid = blockIdx.x * blockDim.x + threadIdx.x;
    if (tid >= NE * NH) return;
    int e = tid >> 1, h = tid & 1;
    int s = src[e], d = dst[e];
    float ev = lrelu(g_as[s * NH + h] + g_ad[d * NH + h]);
    atomicMax(&g_menc[d * NH + h], enc_f(ev));
}
__global__ void k_seg_norm_init() {
    int tid = blockIdx.x * blockDim.x + threadIdx.x;
    if (tid >= N_NODES * NH) return;
    float m = dec_f(g_menc[tid]);
    g_m[tid] = m;
    float es = lrelu(g_as[tid] + g_ad[tid]);  // self-loop
    g_sum[tid] = expf(es - m);
}
__global__ void k_edge_sum(const int* __restrict__ src, const int* __restrict__ dst) {
    int tid = blockIdx.x * blockDim.x + threadIdx.x;
    if (tid >= NE * NH) return;
    int e = tid >> 1, h = tid & 1;
    int s = src[e], d = dst[e];
    float ev = lrelu(g_as[s * NH + h] + g_ad[d * NH + h]);
    atomicAdd(&g_sum[d * NH + h], expf(ev - g_m[d * NH + h]));
}
__global__ void k_gagg_self() {
    int i = blockIdx.x * blockDim.x + threadIdx.x;
    if (i >= N_NODES) return;
    float alpha[NH];
#pragma unroll
    for (int h = 0; h < NH; h++) {
        float es = lrelu(g_as[i * NH + h] + g_ad[i * NH + h]);
        alpha[h] = expf(es - g_m[i * NH + h]) / (g_sum[i * NH + h] + 1e-16f);
    }
#pragma unroll
    for (int c = 0; c < OC; c++)
        g_aggG[i * OC + c] = g_hg[i * OC + c] * alpha[c / NC];
}
__global__ void k_gagg_edge(const int* __restrict__ src, const int* __restrict__ dst) {
    int tid = blockIdx.x * blockDim.x + threadIdx.x;
    if (tid >= NE * 16) return;
    int e = tid >> 4, c = tid & 15;
    if (c >= OC) return;
    int s = src[e], d = dst[e];
    int h = (c >= NC) ? 1 : 0;
    float ev = lrelu(g_as[s * NH + h] + g_ad[d * NH + h]);
    float alpha = expf(ev - g_m[d * NH + h]) / (g_sum[d * NH + h] + 1e-16f);
    atomicAdd(&g_aggG[d * OC + c], g_hg[s * OC + c] * alpha);
}

// ---------------- output: log_softmax(aggG + bg) ----------------
__global__ void k_out(const float* __restrict__ bg, float* __restrict__ out) {
    int i = blockIdx.x * blockDim.x + threadIdx.x;
    if (i >= N_NODES) return;
    float v[OC];
    float mx = -1e30f;
#pragma unroll
    for (int c = 0; c < OC; c++) {
        v[c] = g_aggG[i * OC + c] + bg[c];
        mx = fmaxf(mx, v[c]);
    }
    float s = 0.f;
#pragma unroll
    for (int c = 0; c < OC; c++) s += expf(v[c] - mx);
    float lse = mx + logf(s);
#pragma unroll
    for (int c = 0; c < OC; c++) out[i * OC + c] = v[c] - lse;
}

// ---------------- launch ----------------
extern "C" void kernel_launch(void* const* d_in, const int* in_sizes, int n_in,
                              void* d_out, int out_size) {
    const float* x       = (const float*)d_in[0];
    const int*   ei      = (const int*)  d_in[1];
    const float* W1      = (const float*)d_in[2];
    const float* b1      = (const float*)d_in[3];
    const float* W2      = (const float*)d_in[4];
    const float* b2      = (const float*)d_in[5];
    const float* Wg      = (const float*)d_in[6];
    const float* att_src = (const float*)d_in[7];
    const float* att_dst = (const float*)d_in[8];
    const float* bg      = (const float*)d_in[9];
    float* out = (float*)d_out;

    const int* src = ei;
    const int* dst = ei + NE;

    const int T = 256;
    // degrees / normalization
    k_deg_init<<<(N_NODES + T - 1) / T, T>>>();
    k_deg_edge<<<(NE + T - 1) / T, T>>>(dst);
    k_dinv<<<(N_NODES + T - 1) / T, T>>>();

    // layer 1: transform (tensor cores + 3-stage cp.async), propagate
    k_gemm1<<<(N_NODES + 127) / 128, 256>>>(x, W1);
    k_scatter_self<<<(N_NODES * 16 + T - 1) / T, T>>>();
    k_scatter_edge<<<(NE * 16 + T - 1) / T, T>>>(src, dst);

    // layer 2: relu(agg+b1) @ W2, propagate
    k_gemm2<<<(N_NODES + 15) / 16, 256>>>(b1, W2);
    k_scatter_self<<<(N_NODES * 16 + T - 1) / T, T>>>();
    k_scatter_edge<<<(NE * 16 + T - 1) / T, T>>>(src, dst);

    // GAT head
    k_gat_transform<<<(N_NODES * 32 + T - 1) / T, T>>>(b2, Wg);
    k_node_att<<<(N_NODES * NH + T - 1) / T, T>>>(att_src, att_dst);
    k_edge_max<<<(NE * NH + T - 1) / T, T>>>(src, dst);
    k_seg_norm_init<<<(N_NODES * NH + T - 1) / T, T>>>();
    k_edge_sum<<<(NE * NH + T - 1) / T, T>>>(src, dst);
    k_gagg_self<<<(N_NODES + T - 1) / T, T>>>();
    k_gagg_edge<<<(NE * 16 + T - 1) / T, T>>>(src, dst);

    // output
    k_out<<<(N_NODES + T - 1) / T, T>>>(bg, out);
}